// round 17
// baseline (speedup 1.0000x reference)
#include <cuda_runtime.h>
#include <cuda_fp16.h>
#include <math.h>
#include <stdint.h>

#define B_ 32
#define S_ 4096
#define E_ 512
#define D_ 512
#define H_ 512

#define MT 128              // CTA rows
#define NT 128              // CTA cols (h)
#define KC2 64              // K chunk
#define NCH2 (E_ / KC2)     // 8
#define NTILES (H_ / NT)    // 4
#define A32S 72             // A fp32 smem stride in floats (288B)
#define BSTR 72             // B fp16 smem stride in halves (144B, ldmatrix-safe)
#define A32_B (MT * A32S * 4)     // 36864 B per A stage
#define B16_B (NT * BSTR * 2)     // 18432 B per B stage
#define DSMEM (2 * (A32_B + B16_B))   // 110592

// ---------------- scratch (__device__ globals; no allocs allowed) ----------
__device__ float          g_dec_h[B_ * H_];
__device__ __half         g_Wh[H_ * E_];
__device__ __half         g_Xh[(long)B_ * S_ * E_];   // fp16 X, written by k_gemm
__device__ float          g_scpart[B_ * S_ * NTILES];
__device__ unsigned char  g_flpart[B_ * S_ * NTILES];
__device__ float          g_scores[B_ * S_];
__device__ float          g_attn[B_ * S_];
__device__ float          g_partial[B_ * 8 * E_];

// ---------------- PTX helpers (all base-ISA, valid on plain sm_103) --------
__device__ __forceinline__ uint32_t smem_u32(const void* p) {
    uint32_t a;
    asm("{ .reg .u64 t; cvta.to.shared.u64 t, %1; cvt.u32.u64 %0, t; }" : "=r"(a) : "l"(p));
    return a;
}

__device__ __forceinline__ void mma16816(float* d, const uint32_t* a,
                                         const uint32_t* b) {
    asm volatile(
        "mma.sync.aligned.m16n8k16.row.col.f32.f16.f16.f32 "
        "{%0,%1,%2,%3}, {%4,%5,%6,%7}, {%8,%9}, {%0,%1,%2,%3};"
        : "+f"(d[0]), "+f"(d[1]), "+f"(d[2]), "+f"(d[3])
        : "r"(a[0]), "r"(a[1]), "r"(a[2]), "r"(a[3]), "r"(b[0]), "r"(b[1]));
}

#define LDMX4(r0, r1, r2, r3, addr) \
    asm volatile("ldmatrix.sync.aligned.m8n8.x4.shared.b16 {%0,%1,%2,%3}, [%4];" \
        : "=r"(r0), "=r"(r1), "=r"(r2), "=r"(r3) : "r"(addr))

__device__ __forceinline__ void cp16(uint32_t saddr, const void* gaddr) {
    asm volatile("cp.async.cg.shared.global [%0], [%1], 16;"
                 :: "r"(saddr), "l"(gaddr) : "memory");
}

__device__ __forceinline__ uint32_t packh2(float x, float y) {
    __half2 h = __floats2half2_rn(x, y);
    return *(uint32_t*)&h;
}

// stage one chunk: A fp32 from X, B fp16 from g_Wh; one commit.
__device__ __forceinline__ void stage_chunk(int tid, const float* __restrict__ X,
                                            long mbase, int n0, int ch,
                                            uint32_t sA, uint32_t sB) {
    const float*  Ag = X + mbase * E_ + ch * KC2;
    const __half* Bg = g_Wh + (long)n0 * E_ + ch * KC2;
    #pragma unroll
    for (int it = 0; it < 8; it++) {           // A: 128 rows x 16 x 16B
        int idx = tid + it * 256;
        int row = idx >> 4, q = idx & 15;
        cp16(sA + (uint32_t)((row * A32S + q * 4) * 4), Ag + (long)row * E_ + q * 4);
    }
    #pragma unroll
    for (int it = 0; it < 4; it++) {           // B: 128 rows x 8 x 16B
        int idx = tid + it * 256;
        int row = idx >> 3, q = idx & 7;
        cp16(sB + (uint32_t)((row * BSTR + q * 8) * 2), Bg + (long)row * E_ + q * 8);
    }
    asm volatile("cp.async.commit_group;" ::: "memory");
}

// ---------------------------------------------------------------------------
// Kernel A1: W_enc -> fp16
// ---------------------------------------------------------------------------
__global__ void k_convW(const float* __restrict__ W) {
    int i = blockIdx.x * 512 + threadIdx.x;
    g_Wh[i] = __float2half_rn(W[i]);
}

// ---------------------------------------------------------------------------
// Kernel 0: dec_h[b,h] = decoder_hidden[b,:] . W_dec[h,:] + b_dec[h]
// ---------------------------------------------------------------------------
__global__ void k_dec(const float* __restrict__ dec,
                      const float* __restrict__ Wd,
                      const float* __restrict__ bd) {
    int b  = blockIdx.x >> 2;
    int h0 = (blockIdx.x & 3) * 128;
    int warp = threadIdx.x >> 5, lane = threadIdx.x & 31;
    const float* drow = dec + (long)b * D_;
    for (int h = h0 + warp; h < h0 + 128; h += 8) {
        const float* wrow = Wd + (long)h * D_;
        float s = 0.f;
        for (int e = lane; e < D_; e += 32) s = fmaf(drow[e], wrow[e], s);
        #pragma unroll
        for (int o = 16; o; o >>= 1) s += __shfl_xor_sync(0xffffffffu, s, o);
        if (lane == 0) g_dec_h[b * H_ + h] = s + bd[h];
    }
}

// ---------------------------------------------------------------------------
// Kernel 1: fp16 HMMA GEMM reading fp32 X directly (in-loop conversion to
// fragments, hidden under the MMA floor), cp.async 2-stage pipeline,
// ldmatrix for B, fused Bahdanau score epilogue. ntile==0 CTA also streams
// the converted fp16 X tile to g_Xh for the context kernel.
// ---------------------------------------------------------------------------
__global__ __launch_bounds__(256, 2)
void k_gemm(const float* __restrict__ X,
            const float* __restrict__ benc, const float* __restrict__ v) {
    extern __shared__ char dsm[];
    __shared__ float s_red[MT * 2];
    __shared__ int   s_nzr[MT * 2];
    __shared__ float s_be[NT], s_v[NT], s_dh[NT];

    const int tid = threadIdx.x;
    const int wid = tid >> 5;
    const int lid = tid & 31;
    const int g   = lid >> 2;
    const int t   = lid & 3;
    const int wm  = wid >> 1;     // warp M 0..3
    const int wn  = wid & 1;      // warp N 0..1
    const int mi  = lid >> 3;     // ldmatrix matrix index 0..3
    const int r8  = lid & 7;

    const int mtile = blockIdx.x >> 2;
    const int ntile = blockIdx.x & 3;
    const int n0    = ntile * NT;
    const int b     = mtile >> 5;
    const long mbase = (long)mtile * MT;

    const uint32_t base = smem_u32(dsm);
    const uint32_t sA0 = base;                    // A32 stage 0
    const uint32_t sA1 = base + A32_B;            // A32 stage 1
    const uint32_t sB0 = base + 2 * A32_B;        // B16 stage 0
    const uint32_t sB1 = sB0 + B16_B;             // B16 stage 1

    // ldmatrix per-lane byte offsets for B (within a B stage)
    uint32_t boff[4];
    #pragma unroll
    for (int nb = 0; nb < 4; nb++)
        boff[nb] = (uint32_t)(((wn * 64 + (nb * 2 + (mi >> 1)) * 8 + r8) * BSTR
                               + (mi & 1) * 8) * 2);

    float acc[2][8][4];
    #pragma unroll
    for (int mt = 0; mt < 2; mt++)
        #pragma unroll
        for (int nt = 0; nt < 8; nt++)
            #pragma unroll
            for (int c = 0; c < 4; c++) acc[mt][nt][c] = 0.f;

    // prologue: stage chunks 0,1
    stage_chunk(tid, X, mbase, n0, 0, sA0, sB0);
    stage_chunk(tid, X, mbase, n0, 1, sA1, sB1);

    for (int ch = 0; ch < NCH2; ch++) {
        if (ch == NCH2 - 1)
            asm volatile("cp.async.wait_group 0;" ::: "memory");
        else
            asm volatile("cp.async.wait_group 1;" ::: "memory");
        __syncthreads();

        const uint32_t uA = (ch & 1) ? sA1 : sA0;
        const uint32_t uB = (ch & 1) ? sB1 : sB0;
        const float* As = (const float*)(dsm + (uA - base));

        #pragma unroll
        for (int ks = 0; ks < 4; ks++) {
            const int kb = ks * 16 + t * 2;
            uint32_t ah[2][4], bb[8][2];
            // A fragments: float2 loads from fp32 smem + pack to fp16
            #pragma unroll
            for (int mt = 0; mt < 2; mt++) {
                int rb = wm * 32 + mt * 16 + g;
                float2 f0 = *(const float2*)&As[rb * A32S + kb];
                float2 f1 = *(const float2*)&As[(rb + 8) * A32S + kb];
                float2 f2 = *(const float2*)&As[rb * A32S + kb + 8];
                float2 f3 = *(const float2*)&As[(rb + 8) * A32S + kb + 8];
                ah[mt][0] = packh2(f0.x, f0.y);
                ah[mt][1] = packh2(f1.x, f1.y);
                ah[mt][2] = packh2(f2.x, f2.y);
                ah[mt][3] = packh2(f3.x, f3.y);
            }
            const uint32_t ko = (uint32_t)(ks * 32);
            LDMX4(bb[0][0], bb[0][1], bb[1][0], bb[1][1], uB + boff[0] + ko);
            LDMX4(bb[2][0], bb[2][1], bb[3][0], bb[3][1], uB + boff[1] + ko);
            LDMX4(bb[4][0], bb[4][1], bb[5][0], bb[5][1], uB + boff[2] + ko);
            LDMX4(bb[6][0], bb[6][1], bb[7][0], bb[7][1], uB + boff[3] + ko);
            #pragma unroll
            for (int mt = 0; mt < 2; mt++)
                #pragma unroll
                for (int nt = 0; nt < 8; nt++)
                    mma16816(acc[mt][nt], ah[mt], bb[nt]);
        }

        // ntile==0 CTA: stream converted fp16 X tile chunk to g_Xh
        // (issued after MMAs; overlaps tensor-pipe execution)
        if (ntile == 0) {
            __half* Xo = g_Xh + mbase * E_ + ch * KC2;
            #pragma unroll
            for (int it = 0; it < 8; it++) {
                int idx = tid + it * 256;          // 2048 float4 = 128 rows x 16
                int row = idx >> 4, q = idx & 15;  // q*4 = k offset
                float4 f = *(const float4*)&As[row * A32S + q * 4];
                uint2 u = make_uint2(packh2(f.x, f.y), packh2(f.z, f.w));
                *(uint2*)(Xo + (long)row * E_ + q * 4) = u;
            }
        }
        __syncthreads();
        if (ch + 2 < NCH2)
            stage_chunk(tid, X, mbase, n0, ch + 2,
                        (ch & 1) ? sA1 : sA0, (ch & 1) ? sB1 : sB0);
    }

    // ---- stage bias / v / dec_h for this CTA's 128 h ----------------------
    if (tid < NT) {
        int h = n0 + tid;
        s_be[tid] = benc[h];
        s_v[tid]  = v[h];
        s_dh[tid] = g_dec_h[b * H_ + h];
    }
    __syncthreads();

    // ---- epilogue: y = acc+bias; flag; score += v*tanh(y+dec_h) -----------
    {
        float scr[4] = {0.f, 0.f, 0.f, 0.f};
        int   nzr[4] = {0, 0, 0, 0};
        const int n0w = wn * 64;
        #pragma unroll
        for (int mt = 0; mt < 2; mt++)
            #pragma unroll
            for (int nt = 0; nt < 8; nt++)
                #pragma unroll
                for (int c = 0; c < 4; c++) {
                    int rh = c >> 1, j = c & 1;
                    int hl = n0w + nt * 8 + t * 2 + j;
                    float y = acc[mt][nt][c] + s_be[hl];
                    int ri = mt * 2 + rh;
                    nzr[ri] |= (y != 0.f);
                    scr[ri] += s_v[hl] * tanhf(y + s_dh[hl]);
                }
        #pragma unroll
        for (int o = 1; o <= 2; o <<= 1)
            #pragma unroll
            for (int ri = 0; ri < 4; ri++) {
                scr[ri] += __shfl_xor_sync(0xffffffffu, scr[ri], o);
                nzr[ri] |= __shfl_xor_sync(0xffffffffu, nzr[ri], o);
            }
        if (t == 0) {
            #pragma unroll
            for (int ri = 0; ri < 4; ri++) {
                int row = wm * 32 + (ri >> 1) * 16 + (ri & 1) * 8 + g;
                s_red[row * 2 + wn] = scr[ri];
                s_nzr[row * 2 + wn] = nzr[ri];
            }
        }
    }
    __syncthreads();
    if (tid < MT) {
        float s = s_red[tid * 2] + s_red[tid * 2 + 1];
        int   f = s_nzr[tid * 2] | s_nzr[tid * 2 + 1];
        long gi = (mbase + tid) * NTILES + ntile;
        g_scpart[gi] = s;
        g_flpart[gi] = (unsigned char)(f != 0);
    }
}

// ---------------------------------------------------------------------------
// Kernel 2: combine N-tile partials, then masked softmax with ragged limit
// ---------------------------------------------------------------------------
__global__ void k_softmax() {
    const int b   = blockIdx.x;
    const int tid = threadIdx.x;  // 1024
    const int wid = tid >> 5, lane = tid & 31;
    __shared__ int   ri[32];
    __shared__ float rf[32];
    __shared__ int   s_limit;
    __shared__ float s_max, s_sum;

    int lmin = S_;
    for (int s = tid; s < S_; s += 1024) {
        long m4 = ((long)b * S_ + s) * NTILES;
        float sc = g_scpart[m4] + g_scpart[m4 + 1] + g_scpart[m4 + 2] + g_scpart[m4 + 3];
        int fl = g_flpart[m4] | g_flpart[m4 + 1] | g_flpart[m4 + 2] | g_flpart[m4 + 3];
        g_scores[b * S_ + s] = sc;
        if (!fl) lmin = min(lmin, s);
    }
    #pragma unroll
    for (int o = 16; o; o >>= 1) lmin = min(lmin, __shfl_xor_sync(0xffffffffu, lmin, o));
    if (lane == 0) ri[wid] = lmin;
    __syncthreads();
    if (tid < 32) {
        int vmin = ri[tid];
        #pragma unroll
        for (int o = 16; o; o >>= 1) vmin = min(vmin, __shfl_xor_sync(0xffffffffu, vmin, o));
        if (tid == 0) s_limit = vmin;
    }
    __syncthreads();
    const int limit = s_limit;

    float lmax = -INFINITY;
    for (int s = tid; s < limit; s += 1024) lmax = fmaxf(lmax, g_scores[b * S_ + s]);
    #pragma unroll
    for (int o = 16; o; o >>= 1) lmax = fmaxf(lmax, __shfl_xor_sync(0xffffffffu, lmax, o));
    if (lane == 0) rf[wid] = lmax;
    __syncthreads();
    if (tid < 32) {
        float vmax = rf[tid];
        #pragma unroll
        for (int o = 16; o; o >>= 1) vmax = fmaxf(vmax, __shfl_xor_sync(0xffffffffu, vmax, o));
        if (tid == 0) s_max = vmax;
    }
    __syncthreads();
    const float m = s_max;

    float lsum = 0.f;
    for (int s = tid; s < limit; s += 1024) lsum += expf(g_scores[b * S_ + s] - m);
    #pragma unroll
    for (int o = 16; o; o >>= 1) lsum += __shfl_xor_sync(0xffffffffu, lsum, o);
    __syncthreads();
    if (lane == 0) rf[wid] = lsum;
    __syncthreads();
    if (tid < 32) {
        float vs = rf[tid];
        #pragma unroll
        for (int o = 16; o; o >>= 1) vs += __shfl_xor_sync(0xffffffffu, vs, o);
        if (tid == 0) s_sum = vs;
    }
    __syncthreads();
    const float inv = (s_sum > 0.f) ? (1.f / s_sum) : 0.f;

    for (int s = tid; s < S_; s += 1024)
        g_attn[b * S_ + s] = (s < limit) ? expf(g_scores[b * S_ + s] - m) * inv : 0.f;
}

// ---------------------------------------------------------------------------
// Kernel 3: partial context sums over S-splits, reading fp16 X (half traffic)
// ---------------------------------------------------------------------------
__global__ void k_context_part() {
    const int b  = blockIdx.x;
    const int e  = blockIdx.y * 256 + threadIdx.x;
    const int ss = blockIdx.z;
    const int s0 = ss * (S_ / 8);
    __shared__ float at[S_ / 8];
    for (int i = threadIdx.x; i < S_ / 8; i += 256) at[i] = g_attn[b * S_ + s0 + i];
    __syncthreads();
    const __half* Xp = g_Xh + ((long)b * S_ + s0) * E_ + e;
    float c = 0.f;
    #pragma unroll 8
    for (int s = 0; s < S_ / 8; s++)
        c = fmaf(at[s], __half2float(Xp[(long)s * E_]), c);
    g_partial[(b * 8 + ss) * E_ + e] = c;
}

// ---------------------------------------------------------------------------
// Kernel 4: reduce partials -> output [B,1,E]
// ---------------------------------------------------------------------------
__global__ void k_context_reduce(float* __restrict__ out) {
    const int b = blockIdx.x;
    const int e = threadIdx.x;  // 512
    float s = 0.f;
    #pragma unroll
    for (int k = 0; k < 8; k++) s += g_partial[(b * 8 + k) * E_ + e];
    out[b * E_ + e] = s;
}

extern "C" void kernel_launch(void* const* d_in, const int* in_sizes, int n_in,
                              void* d_out, int out_size) {
    const float* Xenc = (const float*)d_in[0];  // [B,S,E]
    const float* dec  = (const float*)d_in[1];  // [B,D]
    const float* Wenc = (const float*)d_in[2];  // [H,E]
    const float* benc = (const float*)d_in[3];  // [H]
    const float* Wdec = (const float*)d_in[4];  // [H,D]
    const float* bdec = (const float*)d_in[5];  // [H]
    const float* v    = (const float*)d_in[6];  // [H]
    float* out = (float*)d_out;                 // [B,1,E]

    cudaFuncSetAttribute(k_gemm, cudaFuncAttributeMaxDynamicSharedMemorySize, DSMEM);

    k_convW<<<H_, 512>>>(Wenc);
    k_dec<<<B_ * 4, 256>>>(dec, Wdec, bdec);
    k_gemm<<<(B_ * S_ / MT) * NTILES, 256, DSMEM>>>(Xenc, benc, v);
    k_softmax<<<B_, 1024>>>();
    dim3 g3(B_, E_ / 256, 8);
    k_context_part<<<g3, 256>>>();
    k_context_reduce<<<B_, E_>>>(out);
}